// round 10
// baseline (speedup 1.0000x reference)
#include <cuda_runtime.h>
#include <cuda_bf16.h>
#include <math.h>
#include <stdint.h>

// ---------------- problem constants ----------------
#define BB    16
#define FD    2048
#define TT    2048
#define OO    512
#define DD    512
#define CC    20
#define GROUPS 32
#define CH_PER_G (OO / GROUPS)   // 16
#define EPS  1e-5f
#define R_ACT 8
#define NCHUNK 4
#define BPC (BB / NCHUNK)        // 4 batches per chunk
#define GN_NE (CH_PER_G * TT)    // 32768 elems per (b, group)

// ---------------- scratch ----------------
__device__ __align__(128) __nv_bfloat16 g_inbf[(size_t)BB * FD * TT];
__device__ __align__(128) __nv_bfloat16 g_w1bf[(size_t)OO * FD];
__device__ __align__(128) __nv_bfloat16 g_w2bf[(size_t)OO * OO];
__device__ __align__(128) __nv_bfloat16 g_x1bf[(size_t)BB * OO * TT];
__device__ float g_x1[(size_t)BB * OO * TT];
__device__ float g_x2[(size_t)BB * OO * TT];
__device__ float g_cls[(size_t)BB * CC * TT];
__device__ float g_txt[(size_t)BB * CC * TT];
__device__ float g_sum1[BB * GROUPS], g_sq1[BB * GROUPS];
__device__ float g_sum2[BB * GROUPS], g_sq2[BB * GROUPS];
__device__ int   g_lens[2 * BB];

// ---------------- helpers ----------------
__device__ __forceinline__ void cp16(uint32_t sdst, const void* gsrc) {
    asm volatile("cp.async.cg.shared.global [%0], [%1], 16;\n" :: "r"(sdst), "l"(gsrc));
}
#define CP_COMMIT() asm volatile("cp.async.commit_group;\n" ::)
#define CP_WAIT1()  asm volatile("cp.async.wait_group 1;\n" ::)

__device__ __forceinline__ void mma_bf16(float* c, const unsigned* a, const unsigned* b) {
    asm volatile(
        "mma.sync.aligned.m16n8k16.row.col.f32.bf16.bf16.f32 "
        "{%0,%1,%2,%3}, {%4,%5,%6,%7}, {%8,%9}, {%0,%1,%2,%3};\n"
        : "+f"(c[0]), "+f"(c[1]), "+f"(c[2]), "+f"(c[3])
        : "r"(a[0]), "r"(a[1]), "r"(a[2]), "r"(a[3]),
          "r"(b[0]), "r"(b[1]));
}

__device__ __forceinline__ void ldsm_x4(unsigned& r0, unsigned& r1,
                                        unsigned& r2, unsigned& r3, uint32_t a) {
    asm volatile("ldmatrix.sync.aligned.m8n8.x4.shared.b16 {%0,%1,%2,%3}, [%4];"
                 : "=r"(r0), "=r"(r1), "=r"(r2), "=r"(r3) : "r"(a));
}
__device__ __forceinline__ void ldsm_x4_t(unsigned& r0, unsigned& r1,
                                          unsigned& r2, unsigned& r3, uint32_t a) {
    asm volatile("ldmatrix.sync.aligned.m8n8.x4.trans.shared.b16 {%0,%1,%2,%3}, [%4];"
                 : "=r"(r0), "=r"(r1), "=r"(r2), "=r"(r3) : "r"(a));
}

// ============================================================================
// fp32 -> bf16 conversions
// ============================================================================
__global__ void cvtw_kernel(const float* __restrict__ W1, const float* __restrict__ W2)
{
    int i = blockIdx.x * 256 + threadIdx.x;
    if (i < OO * FD) g_w1bf[i] = __float2bfloat16(W1[i]);
    if (i < OO * OO) g_w2bf[i] = __float2bfloat16(W2[i]);
}

// one chunk = BPC batches; also zeroes this chunk's GN1 stat accumulators
__global__ __launch_bounds__(256)
void cvt_in_kernel(const float* __restrict__ in, int b0)
{
    if (blockIdx.x == 0 && threadIdx.x < GROUPS * BPC) {
        int idx = b0 * GROUPS + threadIdx.x;
        g_sum1[idx] = 0.f;
        g_sq1[idx]  = 0.f;
    }
    size_t base = (size_t)b0 * FD * TT;
    size_t i = base + ((size_t)blockIdx.x * 256 + threadIdx.x) * 8;
    float4 v0 = *(const float4*)(in + i);
    float4 v1 = *(const float4*)(in + i + 4);
    __nv_bfloat16 o[8];
    o[0] = __float2bfloat16(v0.x); o[1] = __float2bfloat16(v0.y);
    o[2] = __float2bfloat16(v0.z); o[3] = __float2bfloat16(v0.w);
    o[4] = __float2bfloat16(v1.x); o[5] = __float2bfloat16(v1.y);
    o[6] = __float2bfloat16(v1.z); o[7] = __float2bfloat16(v1.w);
    *(uint4*)(g_inbf + i) = *(uint4*)o;
}

// ============================================================================
// bf16 tensor-core GEMM + fused GroupNorm statistics in the epilogue.
// Stats (sum, sumsq over bias-added outputs) accumulate per (batch, group)
// into g_sum1/g_sq1 (phase 0) or g_sum2/g_sq2 (phase 1) via atomics.
// ============================================================================
#define A_TILE_B (128 * 144)
#define B_TILE_B (64 * 272)
#define STAGE_B  (A_TILE_B + B_TILE_B)
#define GSMEM_BYTES (2 * STAGE_B)

__global__ __launch_bounds__(128, 2)
void gemm_bf16_kernel(const float* __restrict__ bias, int K, int phase, int b0)
{
    const __nv_bfloat16* A  = phase ? g_w2bf : g_w1bf;
    const __nv_bfloat16* Bm = phase ? g_x1bf : g_inbf;
    float*               C  = phase ? g_x2   : g_x1;
    float* g_sumP = phase ? g_sum2 : g_sum1;
    float* g_sqP  = phase ? g_sq2  : g_sq1;

    const int b  = blockIdx.z + b0;
    const int n0 = blockIdx.x * 128;
    const int m0 = blockIdx.y * 128;
    const __nv_bfloat16* Bb = Bm + (size_t)b * K * TT;
    float* Cb = C + (size_t)b * OO * TT;

    extern __shared__ char smem[];
    const uint32_t sbase = (uint32_t)__cvta_generic_to_shared(smem);

    const int tid  = threadIdx.x;
    const int lane = tid & 31;
    const int w    = tid >> 5;
    const int wm   = w >> 1;
    const int wn   = w & 1;
    const int g    = lane >> 2;
    const int t    = lane & 3;

    const int l15 = lane & 15;
    const int lh  = lane >> 4;
    const uint32_t a_off = (uint32_t)((wm * 64 + l15) * 144 + lh * 16);
    const uint32_t b_off = (uint32_t)(l15 * 272 + (wn * 64 + lh * 8) * 2);

    float acc[4][8][4];
#pragma unroll
    for (int i = 0; i < 4; i++)
#pragma unroll
        for (int j = 0; j < 8; j++)
#pragma unroll
            for (int q = 0; q < 4; q++) acc[i][j][q] = 0.f;

    const int nk = K >> 6;

    auto load_tile = [&](int kt) {
        const uint32_t sA = sbase + (kt & 1) * STAGE_B;
        const uint32_t sB = sA + A_TILE_B;
        const int k0 = kt << 6;
#pragma unroll
        for (int i = 0; i < 8; i++) {
            int q   = i * 128 + tid;
            int row = q >> 3;
            int c16 = (q & 7) << 4;
            cp16(sA + row * 144 + c16,
                 (const char*)(A + (size_t)(m0 + row) * K + k0) + c16);
        }
#pragma unroll
        for (int i = 0; i < 8; i++) {
            int q   = i * 128 + tid;
            int row = q >> 4;
            int c16 = (q & 15) << 4;
            cp16(sB + row * 272 + c16,
                 (const char*)(Bb + (size_t)(k0 + row) * TT + n0) + c16);
        }
    };

    load_tile(0); CP_COMMIT();

    unsigned af[2][4][4], bf[2][4][4];

    auto load_frag = [&](int kt, int ks, int buf) {
        const uint32_t sA = sbase + (kt & 1) * STAGE_B + ks * 32;
        const uint32_t sB = sbase + (kt & 1) * STAGE_B + A_TILE_B + ks * 16 * 272;
#pragma unroll
        for (int i = 0; i < 4; i++)
            ldsm_x4(af[buf][i][0], af[buf][i][1], af[buf][i][2], af[buf][i][3],
                    sA + a_off + i * 16 * 144);
#pragma unroll
        for (int jp = 0; jp < 4; jp++)
            ldsm_x4_t(bf[buf][jp][0], bf[buf][jp][1], bf[buf][jp][2], bf[buf][jp][3],
                      sB + b_off + jp * 32);
    };

    for (int kt = 0; kt < nk; kt++) {
        if (kt + 1 < nk) load_tile(kt + 1);
        CP_COMMIT();
        CP_WAIT1();
        __syncthreads();

        load_frag(kt, 0, 0);
#pragma unroll
        for (int ks = 0; ks < 4; ks++) {
            const int cur = ks & 1;
            if (ks < 3) load_frag(kt, ks + 1, cur ^ 1);
#pragma unroll
            for (int i = 0; i < 4; i++) {
#pragma unroll
                for (int jp = 0; jp < 4; jp++) {
                    mma_bf16(acc[i][2 * jp],     af[cur][i], &bf[cur][jp][0]);
                    mma_bf16(acc[i][2 * jp + 1], af[cur][i], &bf[cur][jp][2]);
                }
            }
        }
        __syncthreads();
    }

    // ---- epilogue: bias + store + per-row stat partials ----
    float rsum[8], rsq[8];
#pragma unroll
    for (int r = 0; r < 8; r++) { rsum[r] = 0.f; rsq[r] = 0.f; }

#pragma unroll
    for (int i = 0; i < 4; i++) {
        int row = m0 + wm * 64 + i * 16 + g;
        float b0v = bias[row];
        float b8v = bias[row + 8];
#pragma unroll
        for (int j = 0; j < 8; j++) {
            int col = n0 + wn * 64 + j * 8 + 2 * t;
            float2 v0 = make_float2(acc[i][j][0] + b0v, acc[i][j][1] + b0v);
            float2 v1 = make_float2(acc[i][j][2] + b8v, acc[i][j][3] + b8v);
            *(float2*)(Cb + (size_t)row * TT + col)       = v0;
            *(float2*)(Cb + (size_t)(row + 8) * TT + col) = v1;
            rsum[2 * i]     += v0.x + v0.y;
            rsq[2 * i]      += v0.x * v0.x + v0.y * v0.y;
            rsum[2 * i + 1] += v1.x + v1.y;
            rsq[2 * i + 1]  += v1.x * v1.x + v1.y * v1.y;
        }
    }

    // ---- reduce to per-group sums in smem (tile reads all done) ----
    float* s_red = (float*)smem;     // [0..127]=sum, [128..255]=sumsq
    s_red[tid] = 0.f;
    s_red[tid + 128] = 0.f;
    __syncthreads();
#pragma unroll
    for (int r = 0; r < 8; r++) {
        int row = wm * 64 + (r >> 1) * 16 + (r & 1) * 8 + g;
        atomicAdd(&s_red[row], rsum[r]);
        atomicAdd(&s_red[128 + row], rsq[r]);
    }
    __syncthreads();
    if (tid < 8) {
        float ss = 0.f, sq = 0.f;
#pragma unroll
        for (int r = 0; r < 16; r++) {
            ss += s_red[tid * 16 + r];
            sq += s_red[128 + tid * 16 + r];
        }
        int gidx = b * GROUPS + (m0 >> 4) + tid;
        atomicAdd(&g_sumP[gidx], ss);
        atomicAdd(&g_sqP[gidx], sq);
    }
}

// ============================================================================
// GN1 normalize-only: stats from g_sum1/g_sq1; write masked bf16 g_x1bf.
// Also zeroes g_sum2/g_sq2 for this (b,g) ahead of GEMM2.
// ============================================================================
__global__ void gn1_kernel(const float* __restrict__ gamma,
                           const float* __restrict__ beta,
                           const float* __restrict__ masks)
{
    const int g = blockIdx.x;
    const int b = blockIdx.y;
    const size_t base = ((size_t)b * OO + g * CH_PER_G) * TT;
    const int idx = b * GROUPS + g;

    const float mean = g_sum1[idx] / (float)GN_NE;
    const float var  = g_sq1[idx] / (float)GN_NE - mean * mean;
    const float rstd = rsqrtf(var + EPS);

    if (threadIdx.x == 0) { g_sum2[idx] = 0.f; g_sq2[idx] = 0.f; }

    const float4* xv = (const float4*)(g_x1 + base);
    const float4* mv = (const float4*)(masks + (size_t)b * TT);
    const int NE4 = GN_NE / 4;
    for (int i = threadIdx.x; i < NE4; i += blockDim.x) {
        int c  = i >> 9;
        int tq = i & 511;
        float gm = gamma[g * CH_PER_G + c];
        float bt = beta[g * CH_PER_G + c];
        float4 v = xv[i];
        float4 m = mv[tq];
        __nv_bfloat16 o[4];
        o[0] = __float2bfloat16(((v.x - mean) * rstd * gm + bt) * m.x);
        o[1] = __float2bfloat16(((v.y - mean) * rstd * gm + bt) * m.y);
        o[2] = __float2bfloat16(((v.z - mean) * rstd * gm + bt) * m.z);
        o[3] = __float2bfloat16(((v.w - mean) * rstd * gm + bt) * m.w);
        *(uint2*)(g_x1bf + base + (size_t)i * 4) = *(uint2*)o;
    }
}

// ============================================================================
// Fused GN2-apply + classifier (stats from g_sum2/g_sq2)
// ============================================================================
__global__ void cls_kernel(const float* __restrict__ Wc,
                           const float* __restrict__ bc,
                           const float* __restrict__ gamma,
                           const float* __restrict__ beta,
                           const float* __restrict__ masks)
{
    __shared__ float sW[CC * OO];
    __shared__ float sSc[OO], sSh[OO];
    const int b = blockIdx.y;
    const int t = blockIdx.x * 256 + threadIdx.x;
    for (int i = threadIdx.x; i < CC * OO; i += 256) sW[i] = Wc[i];
    for (int o = threadIdx.x; o < OO; o += 256) {
        int gg = o / CH_PER_G;
        int idx = b * GROUPS + gg;
        float mean = g_sum2[idx] / (float)GN_NE;
        float var  = g_sq2[idx] / (float)GN_NE - mean * mean;
        float rstd = rsqrtf(var + EPS);
        float sc = rstd * gamma[o];
        sSc[o] = sc;
        sSh[o] = beta[o] - mean * sc;
    }
    __syncthreads();

    const float* xb = g_x2 + (size_t)b * OO * TT + t;
    float acc[CC];
#pragma unroll
    for (int c = 0; c < CC; c++) acc[c] = 0.f;
    for (int o = 0; o < OO; o++) {
        float xn = xb[(size_t)o * TT] * sSc[o] + sSh[o];
#pragma unroll
        for (int c = 0; c < CC; c++) acc[c] += xn * sW[c * OO + o];
    }
    float mk = masks[(size_t)b * TT + t];
#pragma unroll
    for (int c = 0; c < CC; c++) {
        float v = 1.f / (1.f + expf(-(mk * acc[c] + bc[c])));
        g_cls[((size_t)b * CC + c) * TT + t] = v;
    }
}

// ============================================================================
// Text head
// ============================================================================
__global__ void txt_kernel(const float* __restrict__ img,
                           const float* __restrict__ proto)
{
    __shared__ float sP[CC * DD];
    const int b = blockIdx.y;
    const int t = blockIdx.x * 128 + threadIdx.x;
    for (int i = threadIdx.x; i < CC * DD; i += 128) sP[i] = proto[i];
    __syncthreads();

    const float* fb = img + ((size_t)b * TT + t) * DD;
    float acc[CC];
#pragma unroll
    for (int c = 0; c < CC; c++) acc[c] = 0.f;
    for (int d = 0; d < DD; d += 4) {
        float4 v = *(const float4*)(fb + d);
#pragma unroll
        for (int c = 0; c < CC; c++) {
            acc[c] += v.x * sP[c * DD + d + 0];
            acc[c] += v.y * sP[c * DD + d + 1];
            acc[c] += v.z * sP[c * DD + d + 2];
            acc[c] += v.w * sP[c * DD + d + 3];
        }
    }
#pragma unroll
    for (int c = 0; c < CC; c++)
        g_txt[((size_t)b * CC + c) * TT + t] = acc[c];
}

// ============================================================================
// Lengths
// ============================================================================
__global__ void len_kernel(const float* __restrict__ masks,
                           const float* __restrict__ img_masks)
{
    const int b = blockIdx.x;
    float sm = 0.f, si = 0.f;
    for (int i = threadIdx.x; i < TT; i += blockDim.x) {
        sm += masks[(size_t)b * TT + i];
        si += img_masks[(size_t)b * TT + i];
    }
    __shared__ float rm[256], ri[256];
    rm[threadIdx.x] = sm; ri[threadIdx.x] = si;
    __syncthreads();
    for (int st = 128; st > 0; st >>= 1) {
        if (threadIdx.x < st) {
            rm[threadIdx.x] += rm[threadIdx.x + st];
            ri[threadIdx.x] += ri[threadIdx.x + st];
        }
        __syncthreads();
    }
    if (threadIdx.x == 0) {
        g_lens[b]      = (int)ri[0];
        g_lens[BB + b] = (int)rm[0];
    }
}

// ============================================================================
// Top-k mean via exact radix-select; head selects txt (0) or cls (1)
// ============================================================================
__device__ __forceinline__ unsigned f2key(float f) {
    unsigned u = __float_as_uint(f);
    return (u & 0x80000000u) ? ~u : (u | 0x80000000u);
}
__device__ __forceinline__ float key2f(unsigned u) {
    return (u & 0x80000000u) ? __uint_as_float(u & 0x7FFFFFFFu)
                             : __uint_as_float(~u);
}

__global__ void topk_kernel(float* __restrict__ out, int head)
{
    const int id = blockIdx.x;            // 0..BB*CC-1
    const int b  = id / CC;
    const int c  = id % CC;

    const float* src = (head == 0 ? g_txt : g_cls) + ((size_t)b * CC + c) * TT;

    __shared__ unsigned keys[TT];
    __shared__ unsigned hist[256];
    __shared__ unsigned s_prefix, s_kk;
    __shared__ float red[256];

    const int tid = threadIdx.x;
    for (int i = tid; i < TT; i += 256) keys[i] = f2key(src[i]);

    int len = g_lens[head * BB + b];
    int k   = len / R_ACT; if (k < 1) k = 1;

    if (tid == 0) { s_prefix = 0; s_kk = (unsigned)k; }
    __syncthreads();

#pragma unroll
    for (int round = 0; round < 4; round++) {
        const int shift = 24 - 8 * round;
        const unsigned prefix = s_prefix;
        hist[tid] = 0;
        __syncthreads();
        for (int i = tid; i < TT; i += 256) {
            unsigned u = keys[i];
            bool in = (round == 0) || ((u >> (shift + 8)) == prefix);
            if (in) atomicAdd(&hist[(u >> shift) & 255u], 1u);
        }
        __syncthreads();
        if (tid == 0) {
            unsigned kk = s_kk, cum = 0;
            int d = 255;
            for (; d > 0; d--) {
                cum += hist[d];
                if (cum >= kk) break;
            }
            if (cum < kk) cum += hist[0];
            s_kk     = kk - (cum - hist[d]);
            s_prefix = (prefix << 8) | (unsigned)d;
        }
        __syncthreads();
    }

    const unsigned T = s_prefix;
    const unsigned kk = s_kk;

    float part = 0.f;
    for (int i = tid; i < TT; i += 256) {
        unsigned u = keys[i];
        if (u > T) part += key2f(u);
    }
    red[tid] = part;
    __syncthreads();
    for (int st = 128; st > 0; st >>= 1) {
        if (tid < st) red[tid] += red[tid + st];
        __syncthreads();
    }
    if (tid == 0) {
        float total = red[0] + (float)kk * key2f(T);
        out[(size_t)head * BB * CC + b * CC + c] = total / (float)k;
    }
}

// ============================================================================
// Streams/events (static init — before harness mem checkpoints)
// ============================================================================
struct StreamPack {
    cudaStream_t s1, s2, sE;
    cudaEvent_t evRoot;
    cudaEvent_t evc[NCHUNK];
    cudaEvent_t ev1, ev2, evE;
    StreamPack() {
        cudaStreamCreateWithFlags(&s1, cudaStreamNonBlocking);
        cudaStreamCreateWithFlags(&s2, cudaStreamNonBlocking);
        cudaStreamCreateWithFlags(&sE, cudaStreamNonBlocking);
        cudaEventCreateWithFlags(&evRoot, cudaEventDisableTiming);
        for (int i = 0; i < NCHUNK; i++)
            cudaEventCreateWithFlags(&evc[i], cudaEventDisableTiming);
        cudaEventCreateWithFlags(&ev1, cudaEventDisableTiming);
        cudaEventCreateWithFlags(&ev2, cudaEventDisableTiming);
        cudaEventCreateWithFlags(&evE, cudaEventDisableTiming);
    }
};
static StreamPack g_sp;

// ============================================================================
// Launch — R6 schedule + fused stats + hidden txt-head top-k
// ============================================================================
extern "C" void kernel_launch(void* const* d_in, const int* in_sizes, int n_in,
                              void* d_out, int out_size)
{
    const float* input = (const float*)d_in[0];
    const float* masks = (const float*)d_in[1];
    const float* proto = (const float*)d_in[2];
    const float* img   = (const float*)d_in[3];
    const float* imgm  = (const float*)d_in[4];
    const float* W1    = (const float*)d_in[5];
    const float* b1    = (const float*)d_in[6];
    const float* g1    = (const float*)d_in[7];
    const float* be1   = (const float*)d_in[8];
    const float* W2    = (const float*)d_in[9];
    const float* b2    = (const float*)d_in[10];
    const float* g2    = (const float*)d_in[11];
    const float* be2   = (const float*)d_in[12];
    const float* Wc    = (const float*)d_in[13];
    const float* bc    = (const float*)d_in[14];
    float* out = (float*)d_out;

    static int setup = 0;
    if (!setup) {
        cudaFuncSetAttribute(gemm_bf16_kernel,
                             cudaFuncAttributeMaxDynamicSharedMemorySize,
                             GSMEM_BYTES);
        setup = 1;
    }

    // -- fork root: side streams join the capture graph --
    cudaEventRecord(g_sp.evRoot, 0);
    cudaStreamWaitEvent(g_sp.s1, g_sp.evRoot, 0);
    cudaStreamWaitEvent(g_sp.s2, g_sp.evRoot, 0);
    cudaStreamWaitEvent(g_sp.sE, g_sp.evRoot, 0);

    // -- stream 0: weight cvt then input cvt chunks --
    cvtw_kernel<<<(OO * FD + 255) / 256, 256>>>(W1, W2);
    const int cvt_blocks = (int)(((size_t)BPC * FD * TT / 8) / 256);
    for (int i = 0; i < NCHUNK; i++) {
        cvt_in_kernel<<<cvt_blocks, 256>>>(input, i * BPC);
        cudaEventRecord(g_sp.evc[i], 0);
    }

    // -- sE: text head + lengths + txt top-k, all hidden under GEMM1 --
    txt_kernel<<<dim3(TT / 128, BB), 128, 0, g_sp.sE>>>(img, proto);
    len_kernel<<<BB, 256, 0, g_sp.sE>>>(masks, imgm);
    topk_kernel<<<BB * CC, 256, 0, g_sp.sE>>>(out, 0);
    cudaEventRecord(g_sp.evE, g_sp.sE);

    // -- GEMM1 chunks alternating on s1/s2 (two concurrent) --
    dim3 cgrid(TT / 128, OO / 128, BPC);
    for (int i = 0; i < NCHUNK; i++) {
        cudaStream_t st = (i & 1) ? g_sp.s2 : g_sp.s1;
        cudaStreamWaitEvent(st, g_sp.evc[i], 0);
        gemm_bf16_kernel<<<cgrid, 128, GSMEM_BYTES, st>>>(b1, FD, 0, i * BPC);
    }
    cudaEventRecord(g_sp.ev1, g_sp.s1);
    cudaEventRecord(g_sp.ev2, g_sp.s2);

    // -- join on stream 0; full-width tail (gn2s eliminated) --
    cudaStreamWaitEvent(0, g_sp.ev1, 0);
    cudaStreamWaitEvent(0, g_sp.ev2, 0);

    gn1_kernel<<<dim3(GROUPS, BB), 256>>>(g1, be1, masks);
    dim3 g2grid(TT / 128, OO / 128, BB);
    gemm_bf16_kernel<<<g2grid, 128, GSMEM_BYTES>>>(b2, OO, 1, 0);
    cls_kernel<<<dim3(TT / 256, BB), 256>>>(Wc, bc, g2, be2, masks);

    cudaStreamWaitEvent(0, g_sp.evE, 0);
    topk_kernel<<<BB * CC, 256>>>(out, 1);
}

// round 11
// speedup vs baseline: 1.2454x; 1.2454x over previous
#include <cuda_runtime.h>
#include <cuda_bf16.h>
#include <math.h>
#include <stdint.h>

// ---------------- problem constants ----------------
#define BB    16
#define FD    2048
#define TT    2048
#define OO    512
#define DD    512
#define CC    20
#define GROUPS 32
#define CH_PER_G (OO / GROUPS)   // 16
#define EPS  1e-5f
#define R_ACT 8
#define NCHUNK 4
#define BPC (BB / NCHUNK)        // 4 batches per chunk

// ---------------- scratch ----------------
__device__ __align__(128) __nv_bfloat16 g_inbf[(size_t)BB * FD * TT];
__device__ __align__(128) __nv_bfloat16 g_w1bf[(size_t)OO * FD];
__device__ __align__(128) __nv_bfloat16 g_w2bf[(size_t)OO * OO];
__device__ __align__(128) __nv_bfloat16 g_x1bf[(size_t)BB * OO * TT];
__device__ float g_x1[(size_t)BB * OO * TT];
__device__ float g_x2[(size_t)BB * OO * TT];
__device__ float g_cls[(size_t)BB * CC * TT];
__device__ float g_txt[(size_t)BB * CC * TT];
__device__ float g_mean2[BB * GROUPS];
__device__ float g_rstd2[BB * GROUPS];
__device__ int   g_lens[2 * BB];

// ---------------- helpers ----------------
__device__ __forceinline__ void cp16(uint32_t sdst, const void* gsrc) {
    asm volatile("cp.async.cg.shared.global [%0], [%1], 16;\n" :: "r"(sdst), "l"(gsrc));
}
#define CP_COMMIT() asm volatile("cp.async.commit_group;\n" ::)
#define CP_WAIT1()  asm volatile("cp.async.wait_group 1;\n" ::)

__device__ __forceinline__ void mma_bf16(float* c, const unsigned* a, const unsigned* b) {
    asm volatile(
        "mma.sync.aligned.m16n8k16.row.col.f32.bf16.bf16.f32 "
        "{%0,%1,%2,%3}, {%4,%5,%6,%7}, {%8,%9}, {%0,%1,%2,%3};\n"
        : "+f"(c[0]), "+f"(c[1]), "+f"(c[2]), "+f"(c[3])
        : "r"(a[0]), "r"(a[1]), "r"(a[2]), "r"(a[3]),
          "r"(b[0]), "r"(b[1]));
}

__device__ __forceinline__ void ldsm_x4(unsigned& r0, unsigned& r1,
                                        unsigned& r2, unsigned& r3, uint32_t a) {
    asm volatile("ldmatrix.sync.aligned.m8n8.x4.shared.b16 {%0,%1,%2,%3}, [%4];"
                 : "=r"(r0), "=r"(r1), "=r"(r2), "=r"(r3) : "r"(a));
}
__device__ __forceinline__ void ldsm_x4_t(unsigned& r0, unsigned& r1,
                                          unsigned& r2, unsigned& r3, uint32_t a) {
    asm volatile("ldmatrix.sync.aligned.m8n8.x4.trans.shared.b16 {%0,%1,%2,%3}, [%4];"
                 : "=r"(r0), "=r"(r1), "=r"(r2), "=r"(r3) : "r"(a));
}

// ============================================================================
// fp32 -> bf16 conversions
// ============================================================================
__global__ void cvtw_kernel(const float* __restrict__ W1, const float* __restrict__ W2)
{
    int i = blockIdx.x * 256 + threadIdx.x;
    if (i < OO * FD) g_w1bf[i] = __float2bfloat16(W1[i]);
    if (i < OO * OO) g_w2bf[i] = __float2bfloat16(W2[i]);
}

__global__ __launch_bounds__(256)
void cvt_in_kernel(const float* __restrict__ in, int b0)
{
    size_t base = (size_t)b0 * FD * TT;
    size_t i = base + ((size_t)blockIdx.x * 256 + threadIdx.x) * 8;
    float4 v0 = *(const float4*)(in + i);
    float4 v1 = *(const float4*)(in + i + 4);
    __nv_bfloat16 o[8];
    o[0] = __float2bfloat16(v0.x); o[1] = __float2bfloat16(v0.y);
    o[2] = __float2bfloat16(v0.z); o[3] = __float2bfloat16(v0.w);
    o[4] = __float2bfloat16(v1.x); o[5] = __float2bfloat16(v1.y);
    o[6] = __float2bfloat16(v1.z); o[7] = __float2bfloat16(v1.w);
    *(uint4*)(g_inbf + i) = *(uint4*)o;
}

// ============================================================================
// bf16 tensor-core GEMM (R6 version — no fused stats)
// ============================================================================
#define A_TILE_B (128 * 144)
#define B_TILE_B (64 * 272)
#define STAGE_B  (A_TILE_B + B_TILE_B)
#define GSMEM_BYTES (2 * STAGE_B)

__global__ __launch_bounds__(128, 2)
void gemm_bf16_kernel(const float* __restrict__ bias, int K, int phase, int b0)
{
    const __nv_bfloat16* A  = phase ? g_w2bf : g_w1bf;
    const __nv_bfloat16* Bm = phase ? g_x1bf : g_inbf;
    float*               C  = phase ? g_x2   : g_x1;

    const int b  = blockIdx.z + b0;
    const int n0 = blockIdx.x * 128;
    const int m0 = blockIdx.y * 128;
    const __nv_bfloat16* Bb = Bm + (size_t)b * K * TT;
    float* Cb = C + (size_t)b * OO * TT;

    extern __shared__ char smem[];
    const uint32_t sbase = (uint32_t)__cvta_generic_to_shared(smem);

    const int tid  = threadIdx.x;
    const int lane = tid & 31;
    const int w    = tid >> 5;
    const int wm   = w >> 1;
    const int wn   = w & 1;
    const int g    = lane >> 2;
    const int t    = lane & 3;

    const int l15 = lane & 15;
    const int lh  = lane >> 4;
    const uint32_t a_off = (uint32_t)((wm * 64 + l15) * 144 + lh * 16);
    const uint32_t b_off = (uint32_t)(l15 * 272 + (wn * 64 + lh * 8) * 2);

    float acc[4][8][4];
#pragma unroll
    for (int i = 0; i < 4; i++)
#pragma unroll
        for (int j = 0; j < 8; j++)
#pragma unroll
            for (int q = 0; q < 4; q++) acc[i][j][q] = 0.f;

    const int nk = K >> 6;

    auto load_tile = [&](int kt) {
        const uint32_t sA = sbase + (kt & 1) * STAGE_B;
        const uint32_t sB = sA + A_TILE_B;
        const int k0 = kt << 6;
#pragma unroll
        for (int i = 0; i < 8; i++) {
            int q   = i * 128 + tid;
            int row = q >> 3;
            int c16 = (q & 7) << 4;
            cp16(sA + row * 144 + c16,
                 (const char*)(A + (size_t)(m0 + row) * K + k0) + c16);
        }
#pragma unroll
        for (int i = 0; i < 8; i++) {
            int q   = i * 128 + tid;
            int row = q >> 4;
            int c16 = (q & 15) << 4;
            cp16(sB + row * 272 + c16,
                 (const char*)(Bb + (size_t)(k0 + row) * TT + n0) + c16);
        }
    };

    load_tile(0); CP_COMMIT();

    unsigned af[2][4][4], bf[2][4][4];

    auto load_frag = [&](int kt, int ks, int buf) {
        const uint32_t sA = sbase + (kt & 1) * STAGE_B + ks * 32;
        const uint32_t sB = sbase + (kt & 1) * STAGE_B + A_TILE_B + ks * 16 * 272;
#pragma unroll
        for (int i = 0; i < 4; i++)
            ldsm_x4(af[buf][i][0], af[buf][i][1], af[buf][i][2], af[buf][i][3],
                    sA + a_off + i * 16 * 144);
#pragma unroll
        for (int jp = 0; jp < 4; jp++)
            ldsm_x4_t(bf[buf][jp][0], bf[buf][jp][1], bf[buf][jp][2], bf[buf][jp][3],
                      sB + b_off + jp * 32);
    };

    for (int kt = 0; kt < nk; kt++) {
        if (kt + 1 < nk) load_tile(kt + 1);
        CP_COMMIT();
        CP_WAIT1();
        __syncthreads();

        load_frag(kt, 0, 0);
#pragma unroll
        for (int ks = 0; ks < 4; ks++) {
            const int cur = ks & 1;
            if (ks < 3) load_frag(kt, ks + 1, cur ^ 1);
#pragma unroll
            for (int i = 0; i < 4; i++) {
#pragma unroll
                for (int jp = 0; jp < 4; jp++) {
                    mma_bf16(acc[i][2 * jp],     af[cur][i], &bf[cur][jp][0]);
                    mma_bf16(acc[i][2 * jp + 1], af[cur][i], &bf[cur][jp][2]);
                }
            }
        }
        __syncthreads();
    }

#pragma unroll
    for (int i = 0; i < 4; i++) {
        int row = m0 + wm * 64 + i * 16 + g;
        float b0v = bias[row];
        float b8v = bias[row + 8];
#pragma unroll
        for (int j = 0; j < 8; j++) {
            int col = n0 + wn * 64 + j * 8 + 2 * t;
            float2 v0 = make_float2(acc[i][j][0] + b0v, acc[i][j][1] + b0v);
            float2 v1 = make_float2(acc[i][j][2] + b8v, acc[i][j][3] + b8v);
            *(float2*)(Cb + (size_t)row * TT + col)       = v0;
            *(float2*)(Cb + (size_t)(row + 8) * TT + col) = v1;
        }
    }
}

// ============================================================================
// GN1 (per chunk): stats on g_x1, write masked bf16 g_x1bf
// ============================================================================
__global__ void gn1_kernel(const float* __restrict__ gamma,
                           const float* __restrict__ beta,
                           const float* __restrict__ masks, int b0)
{
    const int g = blockIdx.x;
    const int b = blockIdx.y + b0;
    const size_t base = ((size_t)b * OO + g * CH_PER_G) * TT;
    const float* xg = g_x1 + base;

    const int NE  = CH_PER_G * TT;
    const int NE4 = NE / 4;

    float s = 0.f, s2 = 0.f;
    const float4* xv = (const float4*)xg;
    for (int i = threadIdx.x; i < NE4; i += blockDim.x) {
        float4 v = xv[i];
        s  += v.x + v.y + v.z + v.w;
        s2 += v.x * v.x + v.y * v.y + v.z * v.z + v.w * v.w;
    }
    __shared__ float rs[256], rs2[256];
    rs[threadIdx.x] = s; rs2[threadIdx.x] = s2;
    __syncthreads();
    for (int st = 128; st > 0; st >>= 1) {
        if (threadIdx.x < st) {
            rs[threadIdx.x]  += rs[threadIdx.x + st];
            rs2[threadIdx.x] += rs2[threadIdx.x + st];
        }
        __syncthreads();
    }
    __shared__ float smean, srstd;
    if (threadIdx.x == 0) {
        float mean = rs[0] / (float)NE;
        float var  = rs2[0] / (float)NE - mean * mean;
        smean = mean; srstd = rsqrtf(var + EPS);
    }
    __syncthreads();
    const float mean = smean, rstd = srstd;

    const float4* mv = (const float4*)(masks + (size_t)b * TT);
    for (int i = threadIdx.x; i < NE4; i += blockDim.x) {
        int c  = i >> 9;
        int tq = i & 511;
        float gm = gamma[g * CH_PER_G + c];
        float bt = beta[g * CH_PER_G + c];
        float4 v = xv[i];
        float4 m = mv[tq];
        __nv_bfloat16 o[4];
        o[0] = __float2bfloat16(((v.x - mean) * rstd * gm + bt) * m.x);
        o[1] = __float2bfloat16(((v.y - mean) * rstd * gm + bt) * m.y);
        o[2] = __float2bfloat16(((v.z - mean) * rstd * gm + bt) * m.z);
        o[3] = __float2bfloat16(((v.w - mean) * rstd * gm + bt) * m.w);
        *(uint2*)(g_x1bf + base + (size_t)i * 4) = *(uint2*)o;
    }
}

// ============================================================================
// GN2 stats (full width)
// ============================================================================
__global__ void gn2s_kernel()
{
    const int g = blockIdx.x;
    const int b = blockIdx.y;
    const float* xg = g_x2 + ((size_t)b * OO + g * CH_PER_G) * TT;

    const int NE  = CH_PER_G * TT;
    const int NE4 = NE / 4;

    float s = 0.f, s2 = 0.f;
    const float4* xv = (const float4*)xg;
    for (int i = threadIdx.x; i < NE4; i += blockDim.x) {
        float4 v = xv[i];
        s  += v.x + v.y + v.z + v.w;
        s2 += v.x * v.x + v.y * v.y + v.z * v.z + v.w * v.w;
    }
    __shared__ float rs[256], rs2[256];
    rs[threadIdx.x] = s; rs2[threadIdx.x] = s2;
    __syncthreads();
    for (int st = 128; st > 0; st >>= 1) {
        if (threadIdx.x < st) {
            rs[threadIdx.x]  += rs[threadIdx.x + st];
            rs2[threadIdx.x] += rs2[threadIdx.x + st];
        }
        __syncthreads();
    }
    if (threadIdx.x == 0) {
        float mean = rs[0] / (float)NE;
        float var  = rs2[0] / (float)NE - mean * mean;
        g_mean2[b * GROUPS + g] = mean;
        g_rstd2[b * GROUPS + g] = rsqrtf(var + EPS);
    }
}

// ============================================================================
// Fused GN2-apply + classifier
// ============================================================================
__global__ void cls_kernel(const float* __restrict__ Wc,
                           const float* __restrict__ bc,
                           const float* __restrict__ gamma,
                           const float* __restrict__ beta,
                           const float* __restrict__ masks)
{
    __shared__ float sW[CC * OO];
    __shared__ float sSc[OO], sSh[OO];
    const int b = blockIdx.y;
    const int t = blockIdx.x * 256 + threadIdx.x;
    for (int i = threadIdx.x; i < CC * OO; i += 256) sW[i] = Wc[i];
    for (int o = threadIdx.x; o < OO; o += 256) {
        int gg = o / CH_PER_G;
        float mean = g_mean2[b * GROUPS + gg];
        float rstd = g_rstd2[b * GROUPS + gg];
        float sc = rstd * gamma[o];
        sSc[o] = sc;
        sSh[o] = beta[o] - mean * sc;
    }
    __syncthreads();

    const float* xb = g_x2 + (size_t)b * OO * TT + t;
    float acc[CC];
#pragma unroll
    for (int c = 0; c < CC; c++) acc[c] = 0.f;
    for (int o = 0; o < OO; o++) {
        float xn = xb[(size_t)o * TT] * sSc[o] + sSh[o];
#pragma unroll
        for (int c = 0; c < CC; c++) acc[c] += xn * sW[c * OO + o];
    }
    float mk = masks[(size_t)b * TT + t];
#pragma unroll
    for (int c = 0; c < CC; c++) {
        float v = 1.f / (1.f + expf(-(mk * acc[c] + bc[c])));
        g_cls[((size_t)b * CC + c) * TT + t] = v;
    }
}

// ============================================================================
// Text head
// ============================================================================
__global__ void txt_kernel(const float* __restrict__ img,
                           const float* __restrict__ proto)
{
    __shared__ float sP[CC * DD];
    const int b = blockIdx.y;
    const int t = blockIdx.x * 128 + threadIdx.x;
    for (int i = threadIdx.x; i < CC * DD; i += 128) sP[i] = proto[i];
    __syncthreads();

    const float* fb = img + ((size_t)b * TT + t) * DD;
    float acc[CC];
#pragma unroll
    for (int c = 0; c < CC; c++) acc[c] = 0.f;
    for (int d = 0; d < DD; d += 4) {
        float4 v = *(const float4*)(fb + d);
#pragma unroll
        for (int c = 0; c < CC; c++) {
            acc[c] += v.x * sP[c * DD + d + 0];
            acc[c] += v.y * sP[c * DD + d + 1];
            acc[c] += v.z * sP[c * DD + d + 2];
            acc[c] += v.w * sP[c * DD + d + 3];
        }
    }
#pragma unroll
    for (int c = 0; c < CC; c++)
        g_txt[((size_t)b * CC + c) * TT + t] = acc[c];
}

// ============================================================================
// Lengths
// ============================================================================
__global__ void len_kernel(const float* __restrict__ masks,
                           const float* __restrict__ img_masks)
{
    const int b = blockIdx.x;
    float sm = 0.f, si = 0.f;
    for (int i = threadIdx.x; i < TT; i += blockDim.x) {
        sm += masks[(size_t)b * TT + i];
        si += img_masks[(size_t)b * TT + i];
    }
    __shared__ float rm[256], ri[256];
    rm[threadIdx.x] = sm; ri[threadIdx.x] = si;
    __syncthreads();
    for (int st = 128; st > 0; st >>= 1) {
        if (threadIdx.x < st) {
            rm[threadIdx.x] += rm[threadIdx.x + st];
            ri[threadIdx.x] += ri[threadIdx.x + st];
        }
        __syncthreads();
    }
    if (threadIdx.x == 0) {
        g_lens[b]      = (int)ri[0];
        g_lens[BB + b] = (int)rm[0];
    }
}

// ============================================================================
// Top-k mean via exact radix-select (both heads, as in R6)
// ============================================================================
__device__ __forceinline__ unsigned f2key(float f) {
    unsigned u = __float_as_uint(f);
    return (u & 0x80000000u) ? ~u : (u | 0x80000000u);
}
__device__ __forceinline__ float key2f(unsigned u) {
    return (u & 0x80000000u) ? __uint_as_float(u & 0x7FFFFFFFu)
                             : __uint_as_float(~u);
}

__global__ void topk_kernel(float* __restrict__ out)
{
    const int id   = blockIdx.x;
    const int head = id / (BB * CC);
    const int r    = id % (BB * CC);
    const int b    = r / CC;
    const int c    = r % CC;

    const float* src = (head == 0 ? g_txt : g_cls) + ((size_t)b * CC + c) * TT;

    __shared__ unsigned keys[TT];
    __shared__ unsigned hist[256];
    __shared__ unsigned s_prefix, s_kk;
    __shared__ float red[256];

    const int tid = threadIdx.x;
    for (int i = tid; i < TT; i += 256) keys[i] = f2key(src[i]);

    int len = g_lens[head * BB + b];
    int k   = len / R_ACT; if (k < 1) k = 1;

    if (tid == 0) { s_prefix = 0; s_kk = (unsigned)k; }
    __syncthreads();

#pragma unroll
    for (int round = 0; round < 4; round++) {
        const int shift = 24 - 8 * round;
        const unsigned prefix = s_prefix;
        hist[tid] = 0;
        __syncthreads();
        for (int i = tid; i < TT; i += 256) {
            unsigned u = keys[i];
            bool in = (round == 0) || ((u >> (shift + 8)) == prefix);
            if (in) atomicAdd(&hist[(u >> shift) & 255u], 1u);
        }
        __syncthreads();
        if (tid == 0) {
            unsigned kk = s_kk, cum = 0;
            int d = 255;
            for (; d > 0; d--) {
                cum += hist[d];
                if (cum >= kk) break;
            }
            if (cum < kk) cum += hist[0];
            s_kk     = kk - (cum - hist[d]);
            s_prefix = (prefix << 8) | (unsigned)d;
        }
        __syncthreads();
    }

    const unsigned T = s_prefix;
    const unsigned kk = s_kk;

    float part = 0.f;
    for (int i = tid; i < TT; i += 256) {
        unsigned u = keys[i];
        if (u > T) part += key2f(u);
    }
    red[tid] = part;
    __syncthreads();
    for (int st = 128; st > 0; st >>= 1) {
        if (tid < st) red[tid] += red[tid + st];
        __syncthreads();
    }
    if (tid == 0) {
        float total = red[0] + (float)kk * key2f(T);
        out[(size_t)head * BB * CC + b * CC + c] = total / (float)k;
    }
}

// ============================================================================
// Streams/events (static init — before harness mem checkpoints)
// ============================================================================
struct StreamPack {
    cudaStream_t s1, s2, sE;
    cudaEvent_t evc[NCHUNK];      // cvt chunk done (stream0)
    cudaEvent_t evg1c[NCHUNK];    // GEMM1 chunk done
    cudaEvent_t evgn1;            // all gn1 chunks done (sE)
    cudaEvent_t ev1, ev2;         // GEMM streams done
    StreamPack() {
        cudaStreamCreateWithFlags(&s1, cudaStreamNonBlocking);
        cudaStreamCreateWithFlags(&s2, cudaStreamNonBlocking);
        cudaStreamCreateWithFlags(&sE, cudaStreamNonBlocking);
        for (int i = 0; i < NCHUNK; i++) {
            cudaEventCreateWithFlags(&evc[i],   cudaEventDisableTiming);
            cudaEventCreateWithFlags(&evg1c[i], cudaEventDisableTiming);
        }
        cudaEventCreateWithFlags(&evgn1, cudaEventDisableTiming);
        cudaEventCreateWithFlags(&ev1, cudaEventDisableTiming);
        cudaEventCreateWithFlags(&ev2, cudaEventDisableTiming);
    }
};
static StreamPack g_sp;

// ============================================================================
// Launch — R6 schedule + gn1 chunks overlapped with GEMM1
// ============================================================================
extern "C" void kernel_launch(void* const* d_in, const int* in_sizes, int n_in,
                              void* d_out, int out_size)
{
    const float* input = (const float*)d_in[0];
    const float* masks = (const float*)d_in[1];
    const float* proto = (const float*)d_in[2];
    const float* img   = (const float*)d_in[3];
    const float* imgm  = (const float*)d_in[4];
    const float* W1    = (const float*)d_in[5];
    const float* b1    = (const float*)d_in[6];
    const float* g1    = (const float*)d_in[7];
    const float* be1   = (const float*)d_in[8];
    const float* W2    = (const float*)d_in[9];
    const float* b2    = (const float*)d_in[10];
    const float* g2    = (const float*)d_in[11];
    const float* be2   = (const float*)d_in[12];
    const float* Wc    = (const float*)d_in[13];
    const float* bc    = (const float*)d_in[14];
    float* out = (float*)d_out;

    static int setup = 0;
    if (!setup) {
        cudaFuncSetAttribute(gemm_bf16_kernel,
                             cudaFuncAttributeMaxDynamicSharedMemorySize,
                             GSMEM_BYTES);
        setup = 1;
    }

    // -- stream 0: weight cvt then input cvt chunks --
    cvtw_kernel<<<(OO * FD + 255) / 256, 256>>>(W1, W2);
    const int cvt_blocks = (int)(((size_t)BPC * FD * TT / 8) / 256);
    for (int i = 0; i < NCHUNK; i++) {
        cvt_in_kernel<<<cvt_blocks, 256>>>(input, i * BPC);
        cudaEventRecord(g_sp.evc[i], 0);
    }

    // -- s2: independent heads first (as in R6) --
    txt_kernel<<<dim3(TT / 128, BB), 128, 0, g_sp.s2>>>(img, proto);
    len_kernel<<<BB, 256, 0, g_sp.s2>>>(masks, imgm);

    // -- GEMM1 chunks alternating on s1/s2; per-chunk events --
    dim3 cgrid(TT / 128, OO / 128, BPC);
    for (int i = 0; i < NCHUNK; i++) {
        cudaStream_t st = (i & 1) ? g_sp.s2 : g_sp.s1;
        cudaStreamWaitEvent(st, g_sp.evc[i], 0);
        gemm_bf16_kernel<<<cgrid, 128, GSMEM_BYTES, st>>>(b1, FD, 0, i * BPC);
        cudaEventRecord(g_sp.evg1c[i], st);
    }
    cudaEventRecord(g_sp.ev1, g_sp.s1);
    cudaEventRecord(g_sp.ev2, g_sp.s2);

    // -- sE: gn1 chunk i right after GEMM1 chunk i (hidden under later chunks) --
    dim3 ngrid(GROUPS, BPC);
    for (int i = 0; i < NCHUNK; i++) {
        cudaStreamWaitEvent(g_sp.sE, g_sp.evg1c[i], 0);
        gn1_kernel<<<ngrid, 256, 0, g_sp.sE>>>(g1, be1, masks, i * BPC);
    }
    cudaEventRecord(g_sp.evgn1, g_sp.sE);

    // -- join on stream 0; serial tail --
    cudaStreamWaitEvent(0, g_sp.evgn1, 0);
    cudaStreamWaitEvent(0, g_sp.ev1, 0);
    cudaStreamWaitEvent(0, g_sp.ev2, 0);

    dim3 g2grid(TT / 128, OO / 128, BB);
    gemm_bf16_kernel<<<g2grid, 128, GSMEM_BYTES>>>(b2, OO, 1, 0);
    gn2s_kernel<<<dim3(GROUPS, BB), 256>>>();
    cls_kernel<<<dim3(TT / 256, BB), 256>>>(Wc, bc, g2, be2, masks);
    topk_kernel<<<2 * BB * CC, 256>>>(out);
}